// round 3
// baseline (speedup 1.0000x reference)
#include <cuda_runtime.h>
#include <cuda_bf16.h>

// DilationLayerExtSE: out[b,c,h,w] = max_{di,dj in 5x5}( zeropad2(x)[b,c,h+di,w+dj] + w[b,c,di,dj] ) + bias[b,c]
// x [8,128,128,128] f32, weight [8,128,5,5], bias [8,128]. stride=1, pad=2.
//
// Streaming-accumulator design (register-pressure optimized):
//   block = one (b,c) plane, 256 threads = 32 col-groups x 8 row-strips.
//   thread: 4 output cols (float4) x 16 output rows.
//   Input rows stream t=0..19 (r = r0-2+t). Each row is loaded as exactly the
//   8 needed floats (LDG.64 halo + LDG.128 body + LDG.64 halo) and folded into
//   the 5 in-flight output-row accumulators: output oh = t-di gets weight row
//   di. Output row oh completes at t = oh+4 and is stored (STG.128).
//   Live state: 8 row + 20 acc + 25 bias-folded weights ~= 61 regs, no spills.
//   Zero padding: OOB rows/cols contribute x=0 (reference pads x with zeros
//   BEFORE adding the weight).

#define H_DIM 128
#define W_DIM 128

__global__ __launch_bounds__(256)
void dilation_kernel(const float* __restrict__ x,
                     const float* __restrict__ wgt,
                     const float* __restrict__ bias,
                     float* __restrict__ out) {
    const int plane = blockIdx.x;            // b*C + c
    const int tid   = threadIdx.x;
    const int cg    = tid & 31;              // column group 0..31
    const int strip = tid >> 5;              // 0..7
    const int colbase = cg << 2;             // output col base (x4 aligned)
    const int r0      = strip << 4;          // first output row of strip

    const float* __restrict__ xp = x   + (size_t)plane * (H_DIM * W_DIM) + colbase;
    float*       __restrict__ op = out + (size_t)plane * (H_DIM * W_DIM) + colbase;
    const float* __restrict__ wp = wgt + plane * 25;
    const float b = __ldg(&bias[plane]);

    // weights with bias folded in
    float wb[25];
#pragma unroll
    for (int k = 0; k < 25; ++k) wb[k] = __ldg(&wp[k]) + b;

    const bool hasA = (cg >= 1);             // left halo exists
    const bool hasC = (cg <= 30);            // right halo exists

    float acc[5][4];                         // 5 in-flight output rows x 4 cols

#pragma unroll
    for (int t = 0; t < 20; ++t) {
        const int r = r0 - 2 + t;            // input row

        // row[i] = x value at global column (colbase - 2 + i), i = 0..7
        float row[8];
        {
            float2 A = make_float2(0.f, 0.f);
            float4 B = make_float4(0.f, 0.f, 0.f, 0.f);
            float2 C = make_float2(0.f, 0.f);
            if ((unsigned)r < (unsigned)H_DIM) {
                const float* rp = xp + r * W_DIM;
                if (hasA) A = __ldg(reinterpret_cast<const float2*>(rp - 2));
                B = __ldg(reinterpret_cast<const float4*>(rp));
                if (hasC) C = __ldg(reinterpret_cast<const float2*>(rp + 4));
            }
            row[0] = A.x; row[1] = A.y;
            row[2] = B.x; row[3] = B.y; row[4] = B.z; row[5] = B.w;
            row[6] = C.x; row[7] = C.y;
        }

        // Fold this row into in-flight outputs oh = t-di (weight row di).
#pragma unroll
        for (int di = 0; di < 5; ++di) {
            const int oh = t - di;
            if (oh < 0 || oh > 15) continue; // compile-time pruned
            float* a = acc[oh % 5];
            if (di == 0) {
                // first tap row of output oh: initialize accumulators
#pragma unroll
                for (int k = 0; k < 4; ++k) a[k] = row[k] + wb[0];
#pragma unroll
                for (int dj = 1; dj < 5; ++dj) {
                    const float wv = wb[dj];
#pragma unroll
                    for (int k = 0; k < 4; ++k)
                        a[k] = fmaxf(a[k], row[k + dj] + wv);
                }
            } else {
#pragma unroll
                for (int dj = 0; dj < 5; ++dj) {
                    const float wv = wb[di * 5 + dj];
#pragma unroll
                    for (int k = 0; k < 4; ++k)
                        a[k] = fmaxf(a[k], row[k + dj] + wv);
                }
            }
        }

        // Output row oh = t-4 just received its last (di=4) taps: store it.
        if (t >= 4) {
            const int oh = t - 4;
            const float* a = acc[oh % 5];
            *reinterpret_cast<float4*>(op + (size_t)(r0 + oh) * W_DIM) =
                make_float4(a[0], a[1], a[2], a[3]);
        }
    }
}

extern "C" void kernel_launch(void* const* d_in, const int* in_sizes, int n_in,
                              void* d_out, int out_size) {
    (void)in_sizes; (void)n_in; (void)out_size;
    const float* x    = (const float*)d_in[0];   // [8,128,128,128]
    const float* wgt  = (const float*)d_in[1];   // [8,128,5,5]
    const float* bias = (const float*)d_in[2];   // [8,128]
    float* out = (float*)d_out;                  // [8,128,128,128]

    dilation_kernel<<<8 * 128, 256>>>(x, wgt, bias, out);
}